// round 5
// baseline (speedup 1.0000x reference)
#include <cuda_runtime.h>
#include <cstdint>

// PPRGo: out[n,:] = sum_k ( mask(wei[n,k]) / (sum_k mask + 1e-12) ) * emb_table[nei[n,k], :]
// N=200000, TOPK=32, EMB=64. nei is int32 on the wire.
//
// One warp per node. Gather uses LDG.128 with TWO neighbor rows per
// instruction (lanes 0-15 -> row 2j, lanes 16-31 -> row 2j+1).
// R4 showed regs=32: ptxas serialized the "8 loads in flight" into
// load-use pairs to hit its occupancy heuristic. __launch_bounds__(256, 3)
// raises the register cap (~85) so all 8 LDG.128 can be batched
// (true MLP=8), trading occupancy 88% -> ~75%.

static constexpr int TOPK = 32;
static constexpr int EMB  = 64;

__global__ __launch_bounds__(256, 3)
void pprgo_kernel(const float* __restrict__ emb,   // [N, 64]
                  const float* __restrict__ wei,   // [N, 32]
                  const int*   __restrict__ nei,   // [N, 32] int32
                  float* __restrict__ out,         // [N, 64]
                  int n_nodes)
{
    const int warp_id = (blockIdx.x * blockDim.x + threadIdx.x) >> 5;
    const int lane    = threadIdx.x & 31;
    if (warp_id >= n_nodes) return;

    const size_t row = (size_t)warp_id * TOPK;

    // --- weight phase: lane k handles neighbor k ---
    float w  = wei[row + lane];
    float m  = (w != 0.0f) ? 1.0f : 0.0f;
    float s  = m;
    #pragma unroll
    for (int o = 16; o > 0; o >>= 1)
        s += __shfl_xor_sync(0xFFFFFFFFu, s, o);
    const float myw = m * (1.0f / (s + 1e-12f));

    const int myidx = nei[row + lane];

    // --- gather phase: half-warp h owns row 2j+h; lane covers 4 floats ---
    const int half = lane >> 4;          // 0 or 1
    const int hl   = lane & 15;          // position within half-warp

    const float4* __restrict__ e4 = reinterpret_cast<const float4*>(emb);

    float4 acc = make_float4(0.f, 0.f, 0.f, 0.f);

    #pragma unroll
    for (int j = 0; j < TOPK / 2; j += 8) {
        int src0 = 2 * (j + 0) + half;
        int src1 = 2 * (j + 1) + half;
        int src2 = 2 * (j + 2) + half;
        int src3 = 2 * (j + 3) + half;
        int src4 = 2 * (j + 4) + half;
        int src5 = 2 * (j + 5) + half;
        int src6 = 2 * (j + 6) + half;
        int src7 = 2 * (j + 7) + half;

        // 32-bit element offsets: max index 200000*16+15 < 2^32
        unsigned o0 = (unsigned)__shfl_sync(0xFFFFFFFFu, myidx, src0) * (EMB/4) + hl;
        unsigned o1 = (unsigned)__shfl_sync(0xFFFFFFFFu, myidx, src1) * (EMB/4) + hl;
        unsigned o2 = (unsigned)__shfl_sync(0xFFFFFFFFu, myidx, src2) * (EMB/4) + hl;
        unsigned o3 = (unsigned)__shfl_sync(0xFFFFFFFFu, myidx, src3) * (EMB/4) + hl;
        unsigned o4 = (unsigned)__shfl_sync(0xFFFFFFFFu, myidx, src4) * (EMB/4) + hl;
        unsigned o5 = (unsigned)__shfl_sync(0xFFFFFFFFu, myidx, src5) * (EMB/4) + hl;
        unsigned o6 = (unsigned)__shfl_sync(0xFFFFFFFFu, myidx, src6) * (EMB/4) + hl;
        unsigned o7 = (unsigned)__shfl_sync(0xFFFFFFFFu, myidx, src7) * (EMB/4) + hl;

        float w0 = __shfl_sync(0xFFFFFFFFu, myw, src0);
        float w1 = __shfl_sync(0xFFFFFFFFu, myw, src1);
        float w2 = __shfl_sync(0xFFFFFFFFu, myw, src2);
        float w3 = __shfl_sync(0xFFFFFFFFu, myw, src3);
        float w4 = __shfl_sync(0xFFFFFFFFu, myw, src4);
        float w5 = __shfl_sync(0xFFFFFFFFu, myw, src5);
        float w6 = __shfl_sync(0xFFFFFFFFu, myw, src6);
        float w7 = __shfl_sync(0xFFFFFFFFu, myw, src7);

        // 8 independent LDG.128 in flight; each covers 2 neighbor rows
        float4 v0 = e4[o0];
        float4 v1 = e4[o1];
        float4 v2 = e4[o2];
        float4 v3 = e4[o3];
        float4 v4 = e4[o4];
        float4 v5 = e4[o5];
        float4 v6 = e4[o6];
        float4 v7 = e4[o7];

        acc.x += w0 * v0.x; acc.y += w0 * v0.y; acc.z += w0 * v0.z; acc.w += w0 * v0.w;
        acc.x += w1 * v1.x; acc.y += w1 * v1.y; acc.z += w1 * v1.z; acc.w += w1 * v1.w;
        acc.x += w2 * v2.x; acc.y += w2 * v2.y; acc.z += w2 * v2.z; acc.w += w2 * v2.w;
        acc.x += w3 * v3.x; acc.y += w3 * v3.y; acc.z += w3 * v3.z; acc.w += w3 * v3.w;
        acc.x += w4 * v4.x; acc.y += w4 * v4.y; acc.z += w4 * v4.z; acc.w += w4 * v4.w;
        acc.x += w5 * v5.x; acc.y += w5 * v5.y; acc.z += w5 * v5.z; acc.w += w5 * v5.w;
        acc.x += w6 * v6.x; acc.y += w6 * v6.y; acc.z += w6 * v6.z; acc.w += w6 * v6.w;
        acc.x += w7 * v7.x; acc.y += w7 * v7.y; acc.z += w7 * v7.z; acc.w += w7 * v7.w;
    }

    // merge the two half-warp partials
    acc.x += __shfl_xor_sync(0xFFFFFFFFu, acc.x, 16);
    acc.y += __shfl_xor_sync(0xFFFFFFFFu, acc.y, 16);
    acc.z += __shfl_xor_sync(0xFFFFFFFFu, acc.z, 16);
    acc.w += __shfl_xor_sync(0xFFFFFFFFu, acc.w, 16);

    if (half == 0) {
        float4* __restrict__ o4p = reinterpret_cast<float4*>(out);
        o4p[(size_t)warp_id * (EMB/4) + hl] = acc;
    }
}

extern "C" void kernel_launch(void* const* d_in, const int* in_sizes, int n_in,
                              void* d_out, int out_size)
{
    const float* emb = (const float*)d_in[0];   // [N, 64]
    const float* wei = (const float*)d_in[1];   // [N, 32]
    const int*   nei = (const int*)d_in[2];     // [N, 32] int32
    float*       out = (float*)d_out;           // [N, 1, 64]

    const int n_nodes = in_sizes[1] / TOPK;     // 200000

    const int threads = 256;                    // 8 warps/block
    const int warps_per_block = threads / 32;
    const int blocks = (n_nodes + warps_per_block - 1) / warps_per_block;

    pprgo_kernel<<<blocks, threads>>>(emb, wei, nei, out, n_nodes);
}

// round 6
// speedup vs baseline: 1.3185x; 1.3185x over previous
#include <cuda_runtime.h>
#include <cstdint>

// PPRGo: out[n,:] = sum_k ( mask(wei[n,k]) / (sum_k mask + 1e-12) ) * emb_table[nei[n,k], :]
// N=200000, TOPK=32, EMB=64. nei is int32 on the wire.
//
// One warp per node; LDG.128 covers TWO neighbor rows per instruction
// (lanes 0-15 -> row 2j, lanes 16-31 -> row 2j+1).
// R4 (regs=32, 56 warps/SM, MLP~3): 88.8us. R5 (regs=80, 24 warps, MLP=8):
// 133us — warp pool dominates. This round targets the middle: ~48 regs,
// 40 warps/SM, software-pipelined batches of 4 LDG.128 so the next batch's
// loads are in flight while the current batch's FMAs retire.

static constexpr int TOPK = 32;
static constexpr int EMB  = 64;

__global__ __launch_bounds__(256, 5)
void pprgo_kernel(const float* __restrict__ emb,   // [N, 64]
                  const float* __restrict__ wei,   // [N, 32]
                  const int*   __restrict__ nei,   // [N, 32] int32
                  float* __restrict__ out,         // [N, 64]
                  int n_nodes)
{
    const int warp_id = (blockIdx.x * blockDim.x + threadIdx.x) >> 5;
    const int lane    = threadIdx.x & 31;
    if (warp_id >= n_nodes) return;

    const size_t row = (size_t)warp_id * TOPK;

    // --- weight phase: lane k handles neighbor k ---
    float w  = wei[row + lane];
    float m  = (w != 0.0f) ? 1.0f : 0.0f;
    float s  = m;
    #pragma unroll
    for (int o = 16; o > 0; o >>= 1)
        s += __shfl_xor_sync(0xFFFFFFFFu, s, o);
    const float myw = m * (1.0f / (s + 1e-12f));

    const int myidx = nei[row + lane];

    // --- gather phase: half-warp h owns row 2j+h; lane covers 4 floats ---
    const int half = lane >> 4;          // 0 or 1
    const int hl   = lane & 15;          // position within half-warp

    const float4* __restrict__ e4 = reinterpret_cast<const float4*>(emb);

    float4 acc = make_float4(0.f, 0.f, 0.f, 0.f);

    // j indexes row-pairs: 16 total, pipelined in batches of 4.
    // Batch b covers j = 4b .. 4b+3; shuffle source lane = 2j + half.
    float4 v[4];
    float  bw[4];

    // prologue: issue batch 0
    #pragma unroll
    for (int t = 0; t < 4; ++t) {
        int src = 2 * t + half;
        unsigned off = (unsigned)__shfl_sync(0xFFFFFFFFu, myidx, src) * (EMB/4) + hl;
        bw[t] = __shfl_sync(0xFFFFFFFFu, myw, src);
        v[t]  = e4[off];
    }

    #pragma unroll
    for (int b = 0; b < 4; ++b) {
        float4 nv[4];
        float  nw[4];
        if (b < 3) {
            // issue batch b+1 before consuming batch b
            #pragma unroll
            for (int t = 0; t < 4; ++t) {
                int src = 2 * (4 * (b + 1) + t) + half;
                unsigned off = (unsigned)__shfl_sync(0xFFFFFFFFu, myidx, src) * (EMB/4) + hl;
                nw[t] = __shfl_sync(0xFFFFFFFFu, myw, src);
                nv[t] = e4[off];
            }
        }

        // consume batch b
        #pragma unroll
        for (int t = 0; t < 4; ++t) {
            acc.x += bw[t] * v[t].x;
            acc.y += bw[t] * v[t].y;
            acc.z += bw[t] * v[t].z;
            acc.w += bw[t] * v[t].w;
        }

        if (b < 3) {
            #pragma unroll
            for (int t = 0; t < 4; ++t) { v[t] = nv[t]; bw[t] = nw[t]; }
        }
    }

    // merge the two half-warp partials
    acc.x += __shfl_xor_sync(0xFFFFFFFFu, acc.x, 16);
    acc.y += __shfl_xor_sync(0xFFFFFFFFu, acc.y, 16);
    acc.z += __shfl_xor_sync(0xFFFFFFFFu, acc.z, 16);
    acc.w += __shfl_xor_sync(0xFFFFFFFFu, acc.w, 16);

    if (half == 0) {
        float4* __restrict__ o4p = reinterpret_cast<float4*>(out);
        o4p[(size_t)warp_id * (EMB/4) + hl] = acc;
    }
}

extern "C" void kernel_launch(void* const* d_in, const int* in_sizes, int n_in,
                              void* d_out, int out_size)
{
    const float* emb = (const float*)d_in[0];   // [N, 64]
    const float* wei = (const float*)d_in[1];   // [N, 32]
    const int*   nei = (const int*)d_in[2];     // [N, 32] int32
    float*       out = (float*)d_out;           // [N, 1, 64]

    const int n_nodes = in_sizes[1] / TOPK;     // 200000

    const int threads = 256;                    // 8 warps/block
    const int warps_per_block = threads / 32;
    const int blocks = (n_nodes + warps_per_block - 1) / warps_per_block;

    pprgo_kernel<<<blocks, threads>>>(emb, wei, nei, out, n_nodes);
}